// round 2
// baseline (speedup 1.0000x reference)
#include <cuda_runtime.h>

#define N_ROWS 32768
#define K_EMB  8192
#define D_DIM  512
#define BM 128
#define BN 128
#define BK 16
#define NTHREADS 256

__device__ float g_enorm[K_EMB];
__device__ int   g_bestIdx[N_ROWS];

// ---------------------------------------------------------------------------
// ||e_k||^2 per codebook row
// ---------------------------------------------------------------------------
__global__ void enorm_kernel(const float* __restrict__ e) {
    __shared__ float red[4];
    const int k = blockIdx.x;
    const float* row = e + (size_t)k * D_DIM;
    float s = 0.f;
    for (int d = threadIdx.x; d < D_DIM; d += 128) {
        float v = row[d];
        s += v * v;
    }
#pragma unroll
    for (int o = 16; o; o >>= 1) s += __shfl_down_sync(0xffffffffu, s, o);
    if ((threadIdx.x & 31) == 0) red[threadIdx.x >> 5] = s;
    __syncthreads();
    if (threadIdx.x == 0) g_enorm[k] = red[0] + red[1] + red[2] + red[3];
}

// ---------------------------------------------------------------------------
// Fused distance-GEMM + argmin.
// Each CTA owns BM=128 rows of x and scans all K embeddings in BN=128 tiles.
// 8x8 register tile per thread, packed into 8x4 f32x2 accumulators driven by
// fma.rn.f32x2 (2x fp32 throughput vs scalar FFMA on sm_103a).
// ---------------------------------------------------------------------------
__global__ __launch_bounds__(NTHREADS, 2) void argmin_kernel(
    const float* __restrict__ x, const float* __restrict__ e) {

    __shared__ __align__(16) float As[BK][BM];
    __shared__ __align__(16) float Bs[BK][BN];
    __shared__ float sD[BM][16];
    __shared__ int   sI[BM][16];

    const int tid = threadIdx.x;
    const int ty  = tid >> 4;   // 0..15 : row group (8 rows each)
    const int tx  = tid & 15;   // 0..15 : col group (8 cols each)
    const int m0  = blockIdx.x * BM;

    float bestD[8];
    int   bestI[8];
#pragma unroll
    for (int i = 0; i < 8; i++) { bestD[i] = 3.4e38f; bestI[i] = 0; }

    // global->smem loader mapping: 512 float4 per tile, 2 per thread
    const int r0 = (tid      ) >> 2, c0 = ((tid      ) & 3) << 2;
    const int r1 = (tid + 256) >> 2, c1 = ((tid + 256) & 3) << 2;

    for (int kt = 0; kt < K_EMB / BN; ++kt) {
        const int k0 = kt * BN;
        unsigned long long acc[8][4];
#pragma unroll
        for (int i = 0; i < 8; i++)
#pragma unroll
            for (int j = 0; j < 4; j++) acc[i][j] = 0ull;

        for (int s = 0; s < D_DIM / BK; ++s) {
            const int d0 = s * BK;
            float4 va0 = *(const float4*)(x + (size_t)(m0 + r0) * D_DIM + d0 + c0);
            float4 va1 = *(const float4*)(x + (size_t)(m0 + r1) * D_DIM + d0 + c1);
            float4 vb0 = *(const float4*)(e + (size_t)(k0 + r0) * D_DIM + d0 + c0);
            float4 vb1 = *(const float4*)(e + (size_t)(k0 + r1) * D_DIM + d0 + c1);
            __syncthreads();   // previous stage compute finished
            As[c0 + 0][r0] = va0.x; As[c0 + 1][r0] = va0.y;
            As[c0 + 2][r0] = va0.z; As[c0 + 3][r0] = va0.w;
            As[c1 + 0][r1] = va1.x; As[c1 + 1][r1] = va1.y;
            As[c1 + 2][r1] = va1.z; As[c1 + 3][r1] = va1.w;
            Bs[c0 + 0][r0] = vb0.x; Bs[c0 + 1][r0] = vb0.y;
            Bs[c0 + 2][r0] = vb0.z; Bs[c0 + 3][r0] = vb0.w;
            Bs[c1 + 0][r1] = vb1.x; Bs[c1 + 1][r1] = vb1.y;
            Bs[c1 + 2][r1] = vb1.z; Bs[c1 + 3][r1] = vb1.w;
            __syncthreads();

#pragma unroll
            for (int d = 0; d < BK; ++d) {
                float4 a0 = *(const float4*)&As[d][ty * 8];
                float4 a1 = *(const float4*)&As[d][ty * 8 + 4];
                ulonglong2 bA = *(const ulonglong2*)&Bs[d][tx * 8];
                ulonglong2 bB = *(const ulonglong2*)&Bs[d][tx * 8 + 4];
                unsigned long long b2[4] = { bA.x, bA.y, bB.x, bB.y };
                float av[8] = { a0.x, a0.y, a0.z, a0.w, a1.x, a1.y, a1.z, a1.w };
#pragma unroll
                for (int i = 0; i < 8; i++) {
                    unsigned long long a2;
                    asm("mov.b64 %0, {%1, %1};" : "=l"(a2) : "f"(av[i]));
#pragma unroll
                    for (int j = 0; j < 4; j++)
                        asm("fma.rn.f32x2 %0, %1, %2, %0;"
                            : "+l"(acc[i][j]) : "l"(a2), "l"(b2[j]));
                }
            }
        }

        // epilogue: dist = ||e||^2 - 2*dot, update running argmin
#pragma unroll
        for (int i = 0; i < 8; i++) {
#pragma unroll
            for (int j = 0; j < 4; j++) {
                float dot0, dot1;
                asm("mov.b64 {%0, %1}, %2;" : "=f"(dot0), "=f"(dot1) : "l"(acc[i][j]));
                const int k = k0 + tx * 8 + j * 2;
                float dist0 = g_enorm[k]     - 2.f * dot0;
                float dist1 = g_enorm[k + 1] - 2.f * dot1;
                if (dist0 < bestD[i]) { bestD[i] = dist0; bestI[i] = k; }
                if (dist1 < bestD[i]) { bestD[i] = dist1; bestI[i] = k + 1; }
            }
        }
    }

    // cross-thread (tx) reduction per row
#pragma unroll
    for (int i = 0; i < 8; i++) {
        sD[ty * 8 + i][tx] = bestD[i];
        sI[ty * 8 + i][tx] = bestI[i];
    }
    __syncthreads();
    if (tid < BM) {
        float bd = sD[tid][0];
        int   bi = sI[tid][0];
#pragma unroll
        for (int t = 1; t < 16; t++) {
            float dv = sD[tid][t];
            int   iv = sI[tid][t];
            if (dv < bd || (dv == bd && iv < bi)) { bd = dv; bi = iv; }
        }
        g_bestIdx[m0 + tid] = bi;
    }
}

// ---------------------------------------------------------------------------
// Writeout: out = [x_q, z_e, z_q]; x_q = x + (z_q - x) (straight-through),
// z_e = x, z_q = embeddings[bestIdx]. float4 vectorized.
// ---------------------------------------------------------------------------
__global__ void writeout_kernel(const float* __restrict__ x,
                                const float* __restrict__ e,
                                float* __restrict__ out) {
    const int ND4 = N_ROWS * (D_DIM / 4);
    int i = blockIdx.x * blockDim.x + threadIdx.x;  // float4 index
    if (i >= ND4) return;
    const int n  = i >> 7;       // 128 float4 per row
    const int d4 = i & 127;
    const int idx = g_bestIdx[n];
    float4 xv = ((const float4*)x)[i];
    float4 ev = ((const float4*)e)[(size_t)idx * 128 + d4];
    float4 xq;
    xq.x = xv.x + (ev.x - xv.x);
    xq.y = xv.y + (ev.y - xv.y);
    xq.z = xv.z + (ev.z - xv.z);
    xq.w = xv.w + (ev.w - xv.w);
    float4* o = (float4*)out;
    o[i]            = xq;   // x_q
    o[ND4 + i]      = xv;   // z_e
    o[2 * ND4 + i]  = ev;   // z_q
}

extern "C" void kernel_launch(void* const* d_in, const int* in_sizes, int n_in,
                              void* d_out, int out_size) {
    const float* x = (const float*)d_in[0];
    const float* e = (const float*)d_in[1];
    float* out = (float*)d_out;

    enorm_kernel<<<K_EMB, 128>>>(e);
    argmin_kernel<<<N_ROWS / BM, NTHREADS>>>(x, e);
    const int ND4 = N_ROWS * (D_DIM / 4);
    writeout_kernel<<<(ND4 + 255) / 256, 256>>>(x, e, out);
}

// round 5
// speedup vs baseline: 7.3353x; 7.3353x over previous
#include <cuda_runtime.h>
#include <cuda_bf16.h>
#include <cstdint>

#define N_ROWS 32768
#define K_EMB  8192
#define D_DIM  512
#define BM 128
#define BN 128
#define BK 64                    // bf16 elems per chunk (128B rows)
#define NKC (D_DIM / BK)         // 8 k-chunks
#define NTILES (K_EMB / BN)      // 64 n-tiles
#define TOTCHUNK (NTILES * NKC)  // 512
#define TILE_B 16384             // 128 rows * 128B
#define STAGE_B (2 * TILE_B)     // A + B
#define NSTAGE 3
#define SMEM_HDR 1024
#define SMEM_TOTAL (SMEM_HDR + NSTAGE * STAGE_B)   // 99328

__device__ __align__(1024) __nv_bfloat16 g_A[(size_t)N_ROWS * D_DIM]; // tiled/swizzled
__device__ __align__(1024) __nv_bfloat16 g_B[(size_t)K_EMB * D_DIM];  // tiled/swizzled
__device__ float g_enorm[K_EMB];
__device__ int   g_cand[N_ROWS * 4];
__device__ int   g_bestIdx[N_ROWS];

// ---------------------------------------------------------------------------
// PTX helpers (baseline sm_90 features only — no tcgen05; ptxas here rejects
// arch-accelerated features on compute_103 target)
// ---------------------------------------------------------------------------
__device__ __forceinline__ uint32_t smem_u32(const void* p) {
    uint32_t a;
    asm("{ .reg .u64 t; cvta.to.shared.u64 t, %1; cvt.u32.u64 %0, t; }" : "=r"(a) : "l"(p));
    return a;
}
__device__ __forceinline__ void mbar_init(uint32_t m, uint32_t cnt) {
    asm volatile("mbarrier.init.shared.b64 [%0], %1;" :: "r"(m), "r"(cnt) : "memory");
}
__device__ __forceinline__ void mbar_expect_tx(uint32_t m, uint32_t bytes) {
    asm volatile("mbarrier.arrive.expect_tx.shared.b64 _, [%0], %1;" :: "r"(m), "r"(bytes) : "memory");
}
__device__ __forceinline__ void mbar_wait(uint32_t m, uint32_t parity) {
    asm volatile(
        "{\n\t.reg .pred P;\n"
        "W_%=:\n\t"
        "mbarrier.try_wait.parity.acquire.cta.shared::cta.b64 P, [%0], %1, 0x989680;\n\t"
        "@P bra D_%=;\n\t"
        "bra W_%=;\n"
        "D_%=:\n\t}"
        :: "r"(m), "r"(parity) : "memory");
}
__device__ __forceinline__ void bulk_g2s(uint32_t dst, const void* src, uint32_t bytes, uint32_t mbar) {
    asm volatile(
        "cp.async.bulk.shared::cluster.global.mbarrier::complete_tx::bytes [%0], [%1], %2, [%3];"
        :: "r"(dst), "l"(src), "r"(bytes), "r"(mbar) : "memory");
}
__device__ __forceinline__ void ldsm4(uint32_t* r, uint32_t addr) {
    asm volatile("ldmatrix.sync.aligned.m8n8.x4.shared.b16 {%0,%1,%2,%3}, [%4];"
                 : "=r"(r[0]), "=r"(r[1]), "=r"(r[2]), "=r"(r[3]) : "r"(addr));
}
__device__ __forceinline__ void mma16816(float* c, const uint32_t* a, uint32_t b0, uint32_t b1) {
    asm volatile(
        "mma.sync.aligned.m16n8k16.row.col.f32.bf16.bf16.f32 "
        "{%0,%1,%2,%3}, {%4,%5,%6,%7}, {%8,%9}, {%0,%1,%2,%3};"
        : "+f"(c[0]), "+f"(c[1]), "+f"(c[2]), "+f"(c[3])
        : "r"(a[0]), "r"(a[1]), "r"(a[2]), "r"(a[3]), "r"(b0), "r"(b1));
}

// ---------------------------------------------------------------------------
// ||e_k||^2
// ---------------------------------------------------------------------------
__global__ void enorm_kernel(const float* __restrict__ e) {
    __shared__ float red[4];
    const int k = blockIdx.x;
    const float* row = e + (size_t)k * D_DIM;
    float s = 0.f;
    for (int d = threadIdx.x; d < D_DIM; d += 128) { float v = row[d]; s += v * v; }
#pragma unroll
    for (int o = 16; o; o >>= 1) s += __shfl_down_sync(0xffffffffu, s, o);
    if ((threadIdx.x & 31) == 0) red[threadIdx.x >> 5] = s;
    __syncthreads();
    if (threadIdx.x == 0) g_enorm[k] = red[0] + red[1] + red[2] + red[3];
}

// ---------------------------------------------------------------------------
// fp32 -> bf16 (round-to-nearest), written pre-swizzled in tile layout:
// tile[t] = 128 rows x 64 cols (128B/row) with SW128 XOR swizzle.
// ---------------------------------------------------------------------------
__device__ __forceinline__ uint4 pack8h(const float* v) {
    unsigned short hh[8];
#pragma unroll
    for (int i = 0; i < 8; i++) hh[i] = __bfloat16_as_ushort(__float2bfloat16(v[i]));
    uint4 H;
    H.x = hh[0] | ((uint32_t)hh[1] << 16); H.y = hh[2] | ((uint32_t)hh[3] << 16);
    H.z = hh[4] | ((uint32_t)hh[5] << 16); H.w = hh[6] | ((uint32_t)hh[7] << 16);
    return H;
}

__global__ void split_x_kernel(const float* __restrict__ x) {
    int gid = blockIdx.x * 256 + threadIdx.x;   // N_ROWS*64 threads
    int n = gid >> 6, d8 = gid & 63;
    const float4* xp = (const float4*)(x + (size_t)n * D_DIM + d8 * 8);
    float4 a = xp[0], b = xp[1];
    float v[8] = {a.x, a.y, a.z, a.w, b.x, b.y, b.z, b.w};
    uint4 H = pack8h(v);
    int tile = (n >> 7) * NKC + (d8 >> 3);
    int boff = (n & 127) * 128 + (d8 & 7) * 16;
    boff ^= (boff >> 3) & 0x70;
    *(uint4*)((char*)g_A + (size_t)tile * TILE_B + boff) = H;
}

__global__ void split_e_kernel(const float* __restrict__ e) {
    int gid = blockIdx.x * 256 + threadIdx.x;   // K_EMB*64 threads
    int k = gid >> 6, d8 = gid & 63;
    const float4* ep = (const float4*)(e + (size_t)k * D_DIM + d8 * 8);
    float4 a = ep[0], b = ep[1];
    float v[8] = {a.x, a.y, a.z, a.w, b.x, b.y, b.z, b.w};
    uint4 H = pack8h(v);
    int tile = (k >> 7) * NKC + (d8 >> 3);
    int boff = (k & 127) * 128 + (d8 & 7) * 16;
    boff ^= (boff >> 3) & 0x70;
    *(uint4*)((char*)g_B + (size_t)tile * TILE_B + boff) = H;
}

// ---------------------------------------------------------------------------
// HMMA GEMM + fused per-row top-2 (merged to top-4 candidates).
// 256 CTAs * 256 thr. Warp grid 4(m) x 2(n); warp tile 32m x 64n.
// 3-stage cp.async.bulk pipeline, thread 0 orchestrates loads.
// ---------------------------------------------------------------------------
__global__ __launch_bounds__(256, 2) void gemm_argmin_kernel() {
    extern __shared__ __align__(128) char smem[];
    const uint32_t sb = smem_u32(smem);
    const int tid = threadIdx.x, l = tid & 31, w = tid >> 5;
    const int wm = w & 3, wn = w >> 2;
    const int bm = blockIdx.x;

    if (tid == 0) {
#pragma unroll
        for (int s = 0; s < NSTAGE; s++) mbar_init(sb + s * 8, 1);
    }
    __syncthreads();

    const char* Ab = (const char*)g_A;
    const char* Bb = (const char*)g_B;
    auto issue = [&](int c) {
        int s = c % NSTAGE;
        uint32_t st = sb + SMEM_HDR + s * STAGE_B;
        mbar_expect_tx(sb + s * 8, STAGE_B);
        bulk_g2s(st,          Ab + ((size_t)bm * NKC + (c & 7)) * TILE_B, TILE_B, sb + s * 8);
        bulk_g2s(st + TILE_B, Bb + ((size_t)(c >> 3) * NKC + (c & 7)) * TILE_B, TILE_B, sb + s * 8);
    };
    if (tid == 0) { issue(0); issue(1); issue(2); }

    // per-thread addressing constants
    const int lrA = (l & 7) + ((l >> 3) & 1) * 8;            // A row-in-16
    const int lrB = (l & 7) + ((l >> 4) & 1) * 8;            // B row-in-16
    const int cA  = (l >> 4);                                 // A col16 offset
    const int cB  = ((l >> 3) & 1);                           // B col16 offset
    const int swz = (l & 7);

    float td[4][2]; int ti[4][2];
#pragma unroll
    for (int i = 0; i < 4; i++) { td[i][0] = td[i][1] = 3.4e38f; ti[i][0] = ti[i][1] = 0; }

    for (int nt = 0; nt < NTILES; ++nt) {
        float acc[2][8][4];
#pragma unroll
        for (int mi = 0; mi < 2; mi++)
#pragma unroll
            for (int nf = 0; nf < 8; nf++)
#pragma unroll
                for (int j = 0; j < 4; j++) acc[mi][nf][j] = 0.f;

        for (int kc = 0; kc < NKC; ++kc) {
            const int c = nt * NKC + kc, s = c % NSTAGE;
            mbar_wait(sb + s * 8, (c / NSTAGE) & 1);
            const uint32_t aB = sb + SMEM_HDR + s * STAGE_B;
            const uint32_t bB = aB + TILE_B;
#pragma unroll
            for (int ks = 0; ks < 4; ks++) {
                uint32_t am[2][4];
#pragma unroll
                for (int mi = 0; mi < 2; mi++) {
                    uint32_t addr = aB + (uint32_t)(wm * 32 + mi * 16 + lrA) * 128
                                       + (uint32_t)(((ks * 2 + cA) ^ swz) << 4);
                    ldsm4(am[mi], addr);
                }
#pragma unroll
                for (int nb = 0; nb < 4; nb++) {
                    uint32_t br[4];
                    uint32_t addr = bB + (uint32_t)(wn * 64 + nb * 16 + lrB) * 128
                                       + (uint32_t)(((ks * 2 + cB) ^ swz) << 4);
                    ldsm4(br, addr);
#pragma unroll
                    for (int mi = 0; mi < 2; mi++) {
                        mma16816(acc[mi][nb * 2 + 0], am[mi], br[0], br[1]);
                        mma16816(acc[mi][nb * 2 + 1], am[mi], br[2], br[3]);
                    }
                }
            }
            __syncthreads();
            if (tid == 0 && c + 3 < TOTCHUNK) issue(c + 3);
        }

        // epilogue: dist = ||e||^2 - 2*dot ; per-thread top-2 per row
#pragma unroll
        for (int mi = 0; mi < 2; mi++)
#pragma unroll
            for (int r2 = 0; r2 < 2; r2++) {
                const int ri = mi * 2 + r2;
#pragma unroll
                for (int nf = 0; nf < 8; nf++)
#pragma unroll
                    for (int d = 0; d < 2; d++) {
                        const int col = nt * BN + wn * 64 + nf * 8 + (l & 3) * 2 + d;
                        float dist = __ldg(&g_enorm[col]) - 2.f * acc[mi][nf][r2 * 2 + d];
                        if (dist < td[ri][0]) {
                            td[ri][1] = td[ri][0]; ti[ri][1] = ti[ri][0];
                            td[ri][0] = dist;      ti[ri][0] = col;
                        } else if (dist < td[ri][1]) {
                            td[ri][1] = dist; ti[ri][1] = col;
                        }
                    }
            }
    }

    // merge 8 contributors x top-2 -> top-4 candidates per row
    __syncthreads();
    float* sD = (float*)(smem + SMEM_HDR);            // [128][16]
    int*   sI = (int*)(smem + SMEM_HDR + 128 * 16 * 4);
#pragma unroll
    for (int mi = 0; mi < 2; mi++)
#pragma unroll
        for (int r2 = 0; r2 < 2; r2++) {
            const int ri = mi * 2 + r2;
            const int row = wm * 32 + mi * 16 + r2 * 8 + (l >> 2);
            const int slot = (wn * 4 + (l & 3)) * 2;
            sD[row * 16 + slot] = td[ri][0]; sI[row * 16 + slot] = ti[ri][0];
            sD[row * 16 + slot + 1] = td[ri][1]; sI[row * 16 + slot + 1] = ti[ri][1];
        }
    __syncthreads();
    if (tid < BM) {
        float dv[16]; int iv[16];
#pragma unroll
        for (int t = 0; t < 16; t++) { dv[t] = sD[tid * 16 + t]; iv[t] = sI[tid * 16 + t]; }
        const int rg = bm * BM + tid;
#pragma unroll
        for (int j = 0; j < 4; j++) {
            float bd = dv[0]; int bi = iv[0], bt = 0;
#pragma unroll
            for (int t = 1; t < 16; t++)
                if (dv[t] < bd || (dv[t] == bd && iv[t] < bi)) { bd = dv[t]; bi = iv[t]; bt = t; }
            g_cand[rg * 4 + j] = bi;
            dv[bt] = 3.4e38f;
        }
    }
}

// ---------------------------------------------------------------------------
// Exact fp32 rescore of the 4 candidates per row.
// ---------------------------------------------------------------------------
__global__ void rescore_kernel(const float* __restrict__ x, const float* __restrict__ e) {
    const int row = blockIdx.x * 8 + (threadIdx.x >> 5);
    const int lane = threadIdx.x & 31;
    int c[4];
#pragma unroll
    for (int j = 0; j < 4; j++) c[j] = g_cand[row * 4 + j];
    const float* xr = x + (size_t)row * D_DIM;
    float s[4] = {0.f, 0.f, 0.f, 0.f};
    for (int d = lane; d < D_DIM; d += 32) {
        float xv = xr[d];
#pragma unroll
        for (int j = 0; j < 4; j++) s[j] += xv * e[(size_t)c[j] * D_DIM + d];
    }
#pragma unroll
    for (int o = 16; o; o >>= 1)
#pragma unroll
        for (int j = 0; j < 4; j++) s[j] += __shfl_down_sync(0xffffffffu, s[j], o);
    if (lane == 0) {
        float bd = 3.4e38f; int bi = 0x7fffffff;
#pragma unroll
        for (int j = 0; j < 4; j++) {
            float dj = g_enorm[c[j]] - 2.f * s[j];
            if (dj < bd || (dj == bd && c[j] < bi)) { bd = dj; bi = c[j]; }
        }
        g_bestIdx[row] = bi;
    }
}

// ---------------------------------------------------------------------------
// Writeout: out = [x_q, z_e, z_q]
// ---------------------------------------------------------------------------
__global__ void writeout_kernel(const float* __restrict__ x,
                                const float* __restrict__ e,
                                float* __restrict__ out) {
    const int ND4 = N_ROWS * (D_DIM / 4);
    int i = blockIdx.x * blockDim.x + threadIdx.x;
    if (i >= ND4) return;
    const int n = i >> 7, d4 = i & 127;
    const int idx = g_bestIdx[n];
    float4 xv = ((const float4*)x)[i];
    float4 ev = ((const float4*)e)[(size_t)idx * 128 + d4];
    float4 xq;
    xq.x = xv.x + (ev.x - xv.x);
    xq.y = xv.y + (ev.y - xv.y);
    xq.z = xv.z + (ev.z - xv.z);
    xq.w = xv.w + (ev.w - xv.w);
    float4* o = (float4*)out;
    o[i] = xq;               // x_q
    o[ND4 + i] = xv;         // z_e
    o[2 * ND4 + i] = ev;     // z_q
}

extern "C" void kernel_launch(void* const* d_in, const int* in_sizes, int n_in,
                              void* d_out, int out_size) {
    const float* x = (const float*)d_in[0];
    const float* e = (const float*)d_in[1];
    float* out = (float*)d_out;

    // unconditional (no static guards — harness rule); not a stream op, capture-safe
    cudaFuncSetAttribute(gemm_argmin_kernel,
                         cudaFuncAttributeMaxDynamicSharedMemorySize, SMEM_TOTAL);

    split_x_kernel<<<N_ROWS * 64 / 256, 256>>>(x);
    split_e_kernel<<<K_EMB * 64 / 256, 256>>>(e);
    enorm_kernel<<<K_EMB, 128>>>(e);
    gemm_argmin_kernel<<<N_ROWS / BM, 256, SMEM_TOTAL>>>();
    rescore_kernel<<<N_ROWS / 8, 256>>>(x, e);
    const int ND4 = N_ROWS * (D_DIM / 4);
    writeout_kernel<<<(ND4 + 255) / 256, 256>>>(x, e, out);
}

// round 7
// speedup vs baseline: 8.2158x; 1.1200x over previous
#include <cuda_runtime.h>
#include <cuda_bf16.h>
#include <cstdint>

#define N_ROWS 32768
#define K_EMB  8192
#define D_DIM  512
#define BM 128
#define BN 128
#define BK 64                    // bf16 elems per chunk (128B rows)
#define NKC (D_DIM / BK)         // 8 k-chunks
#define NTILES (K_EMB / BN)      // 64 n-tiles
#define TILE_B 16384             // 128 rows * 128B
#define STAGE_B (2 * TILE_B)     // A + B
#define NSTAGE 3
#define GRID_P 296               // 2 CTAs x 148 SMs, all resident
#define NT_U 8                   // n-tiles per work unit
#define NUNITS (256 * 8)         // (m-tile, n-eighth) units = 2048
#define SMEM_HDR 1024            // barriers
#define SMEM_MRG 4096            // 128 rows x 4 (d,i) pairs
#define SMEM_STAGES (SMEM_HDR + SMEM_MRG)
#define SMEM_TOTAL (SMEM_STAGES + NSTAGE * STAGE_B)   // 103424 -> 2 CTA/SM

__device__ __align__(1024) __nv_bfloat16 g_A[(size_t)N_ROWS * D_DIM]; // tiled/swizzled
__device__ __align__(1024) __nv_bfloat16 g_B[(size_t)K_EMB * D_DIM];  // tiled/swizzled
__device__ float g_enorm[K_EMB];
__device__ float g_pd[(size_t)N_ROWS * 16];
__device__ int   g_pi[(size_t)N_ROWS * 16];
__device__ int   g_cand[N_ROWS * 4];
__device__ int   g_bestIdx[N_ROWS];

// ---------------------------------------------------------------------------
// PTX helpers (baseline features only — ptxas rejects tcgen05 on compute_103)
// ---------------------------------------------------------------------------
__device__ __forceinline__ uint32_t smem_u32(const void* p) {
    uint32_t a;
    asm("{ .reg .u64 t; cvta.to.shared.u64 t, %1; cvt.u32.u64 %0, t; }" : "=r"(a) : "l"(p));
    return a;
}
__device__ __forceinline__ void mbar_init(uint32_t m, uint32_t cnt) {
    asm volatile("mbarrier.init.shared.b64 [%0], %1;" :: "r"(m), "r"(cnt) : "memory");
}
__device__ __forceinline__ void mbar_arrive(uint32_t m) {
    asm volatile("mbarrier.arrive.shared.b64 _, [%0];" :: "r"(m) : "memory");
}
__device__ __forceinline__ void mbar_expect_tx(uint32_t m, uint32_t bytes) {
    asm volatile("mbarrier.arrive.expect_tx.shared.b64 _, [%0], %1;" :: "r"(m), "r"(bytes) : "memory");
}
__device__ __forceinline__ void mbar_wait(uint32_t m, uint32_t parity) {
    asm volatile(
        "{\n\t.reg .pred P;\n"
        "W_%=:\n\t"
        "mbarrier.try_wait.parity.acquire.cta.shared::cta.b64 P, [%0], %1, 0x989680;\n\t"
        "@P bra D_%=;\n\t"
        "bra W_%=;\n"
        "D_%=:\n\t}"
        :: "r"(m), "r"(parity) : "memory");
}
__device__ __forceinline__ void bulk_g2s(uint32_t dst, const void* src, uint32_t bytes, uint32_t mbar) {
    asm volatile(
        "cp.async.bulk.shared::cluster.global.mbarrier::complete_tx::bytes [%0], [%1], %2, [%3];"
        :: "r"(dst), "l"(src), "r"(bytes), "r"(mbar) : "memory");
}
__device__ __forceinline__ void ldsm4(uint32_t* r, uint32_t addr) {
    asm volatile("ldmatrix.sync.aligned.m8n8.x4.shared.b16 {%0,%1,%2,%3}, [%4];"
                 : "=r"(r[0]), "=r"(r[1]), "=r"(r[2]), "=r"(r[3]) : "r"(addr));
}
__device__ __forceinline__ void mma16816(float* c, const uint32_t* a, uint32_t b0, uint32_t b1) {
    asm volatile(
        "mma.sync.aligned.m16n8k16.row.col.f32.bf16.bf16.f32 "
        "{%0,%1,%2,%3}, {%4,%5,%6,%7}, {%8,%9}, {%0,%1,%2,%3};"
        : "+f"(c[0]), "+f"(c[1]), "+f"(c[2]), "+f"(c[3])
        : "r"(a[0]), "r"(a[1]), "r"(a[2]), "r"(a[3]), "r"(b0), "r"(b1));
}

// ---------------------------------------------------------------------------
// ||e_k||^2
// ---------------------------------------------------------------------------
__global__ void enorm_kernel(const float* __restrict__ e) {
    __shared__ float red[4];
    const int k = blockIdx.x;
    const float* row = e + (size_t)k * D_DIM;
    float s = 0.f;
    for (int d = threadIdx.x; d < D_DIM; d += 128) { float v = row[d]; s += v * v; }
#pragma unroll
    for (int o = 16; o; o >>= 1) s += __shfl_down_sync(0xffffffffu, s, o);
    if ((threadIdx.x & 31) == 0) red[threadIdx.x >> 5] = s;
    __syncthreads();
    if (threadIdx.x == 0) g_enorm[k] = red[0] + red[1] + red[2] + red[3];
}

// ---------------------------------------------------------------------------
// fp32 -> bf16, pre-swizzled tile layout: tile = 128 rows x 64 cols (128B/row),
// SW128 XOR swizzle.
// ---------------------------------------------------------------------------
__device__ __forceinline__ uint4 pack8h(const float* v) {
    unsigned short hh[8];
#pragma unroll
    for (int i = 0; i < 8; i++) hh[i] = __bfloat16_as_ushort(__float2bfloat16(v[i]));
    uint4 H;
    H.x = hh[0] | ((uint32_t)hh[1] << 16); H.y = hh[2] | ((uint32_t)hh[3] << 16);
    H.z = hh[4] | ((uint32_t)hh[5] << 16); H.w = hh[6] | ((uint32_t)hh[7] << 16);
    return H;
}

__global__ void split_x_kernel(const float* __restrict__ x) {
    int gid = blockIdx.x * 256 + threadIdx.x;   // N_ROWS*64 threads
    int n = gid >> 6, d8 = gid & 63;
    const float4* xp = (const float4*)(x + (size_t)n * D_DIM + d8 * 8);
    float4 a = xp[0], b = xp[1];
    float v[8] = {a.x, a.y, a.z, a.w, b.x, b.y, b.z, b.w};
    uint4 H = pack8h(v);
    int tile = (n >> 7) * NKC + (d8 >> 3);
    int boff = (n & 127) * 128 + (d8 & 7) * 16;
    boff ^= (boff >> 3) & 0x70;
    *(uint4*)((char*)g_A + (size_t)tile * TILE_B + boff) = H;
}

__global__ void split_e_kernel(const float* __restrict__ e) {
    int gid = blockIdx.x * 256 + threadIdx.x;   // K_EMB*64 threads
    int k = gid >> 6, d8 = gid & 63;
    const float4* ep = (const float4*)(e + (size_t)k * D_DIM + d8 * 8);
    float4 a = ep[0], b = ep[1];
    float v[8] = {a.x, a.y, a.z, a.w, b.x, b.y, b.z, b.w};
    uint4 H = pack8h(v);
    int tile = (k >> 7) * NKC + (d8 >> 3);
    int boff = (k & 127) * 128 + (d8 & 7) * 16;
    boff ^= (boff >> 3) & 0x70;
    *(uint4*)((char*)g_B + (size_t)tile * TILE_B + boff) = H;
}

// ---------------------------------------------------------------------------
// Persistent HMMA GEMM + per-unit top-2 per row.
// 296 CTAs (2/SM, all resident). Units = (m-tile, n-eighth), static stride-296.
// Per-warp mbarrier pipeline: full[s] tx-barrier, empty[s] count-8; no
// per-chunk __syncthreads. Warp grid 4(m) x 2(n); warp tile 32m x 64n.
// ---------------------------------------------------------------------------
__global__ __launch_bounds__(256, 2) void gemm_argmin_kernel() {
    extern __shared__ __align__(1024) char smem[];
    const uint32_t sb = smem_u32(smem);
    const int tid = threadIdx.x, l = tid & 31, w = tid >> 5;
    const int wm = w & 3, wn = w >> 2;
    const int b = blockIdx.x;
    const int cnt = (b < (NUNITS % GRID_P)) ? (NUNITS / GRID_P + 1) : (NUNITS / GRID_P);
    const int END = cnt * (NT_U * NKC);            // chunks in this CTA's stream

    // full[s] @ sb + s*8 ; empty[s] @ sb + 64 + s*8
    if (tid == 0) {
#pragma unroll
        for (int s = 0; s < NSTAGE; s++) { mbar_init(sb + s * 8, 1); mbar_init(sb + 64 + s * 8, 8); }
    }
    __syncthreads();

    const char* Ab = (const char*)g_A;
    const char* Bb = (const char*)g_B;
    auto issue = [&](int g) {
        int j = g >> 6, r = g & 63;
        int u = b + j * GRID_P;
        int m = u >> 3, ne = u & 7;
        int nt = ne * NT_U + (r >> 3), kc = r & 7;
        int s = g % NSTAGE;
        uint32_t st = sb + SMEM_STAGES + s * STAGE_B;
        mbar_expect_tx(sb + s * 8, STAGE_B);
        bulk_g2s(st,          Ab + ((size_t)m * NKC + kc) * TILE_B, TILE_B, sb + s * 8);
        bulk_g2s(st + TILE_B, Bb + ((size_t)nt * NKC + kc) * TILE_B, TILE_B, sb + s * 8);
    };
    if (tid == 0) { issue(0); issue(1); issue(2); }   // END >= 384 always

    // per-thread addressing constants
    const int lrA = (l & 7) + ((l >> 3) & 1) * 8;            // A row-in-16
    const int lrB = (l & 7) + ((l >> 4) & 1) * 8;            // B row-in-16
    const int cA  = (l >> 4);                                 // A col16 offset
    const int cB  = ((l >> 3) & 1);                           // B col16 offset
    const int swz = (l & 7);

    float* sMD = (float*)(smem + SMEM_HDR);                   // [128][4]
    int*   sMI = (int*)(smem + SMEM_HDR + 128 * 4 * 4);       // [128][4]

    int g = 0;
    for (int j = 0; j < cnt; ++j) {
        const int u = b + j * GRID_P;
        const int m = u >> 3, ne = u & 7;

        float td[4][2]; int ti[4][2];
#pragma unroll
        for (int i = 0; i < 4; i++) { td[i][0] = td[i][1] = 3.4e38f; ti[i][0] = ti[i][1] = 0; }

        for (int ntl = 0; ntl < NT_U; ++ntl) {
            float acc[2][8][4];
#pragma unroll
            for (int mi = 0; mi < 2; mi++)
#pragma unroll
                for (int nf = 0; nf < 8; nf++)
#pragma unroll
                    for (int q = 0; q < 4; q++) acc[mi][nf][q] = 0.f;

            for (int kc = 0; kc < NKC; ++kc, ++g) {
                const int s = g % NSTAGE;
                const uint32_t phase = (uint32_t)((g / NSTAGE) & 1);
                mbar_wait(sb + s * 8, phase);
                const uint32_t aB = sb + SMEM_STAGES + s * STAGE_B;
                const uint32_t bB = aB + TILE_B;
#pragma unroll
                for (int ks = 0; ks < 4; ks++) {
                    uint32_t am[2][4];
#pragma unroll
                    for (int mi = 0; mi < 2; mi++) {
                        uint32_t addr = aB + (uint32_t)(wm * 32 + mi * 16 + lrA) * 128
                                           + (uint32_t)(((ks * 2 + cA) ^ swz) << 4);
                        ldsm4(am[mi], addr);
                    }
#pragma unroll
                    for (int nb = 0; nb < 4; nb++) {
                        uint32_t br[4];
                        uint32_t addr = bB + (uint32_t)(wn * 64 + nb * 16 + lrB) * 128
                                           + (uint32_t)(((ks * 2 + cB) ^ swz) << 4);
                        ldsm4(br, addr);
#pragma unroll
                        for (int mi = 0; mi < 2; mi++) {
                            mma16816(acc[mi][nb * 2 + 0], am[mi], br[0], br[1]);
                            mma16816(acc[mi][nb * 2 + 1], am[mi], br[2], br[3]);
                        }
                    }
                }
                if (l == 0) mbar_arrive(sb + 64 + s * 8);     // this warp done with stage s
                if (tid == 0 && g + 3 < END) {
                    mbar_wait(sb + 64 + s * 8, phase);        // all 8 warps done w/ chunk g
                    issue(g + 3);
                }
            }

            // epilogue: dist = ||e||^2 - 2*dot ; per-thread top-2 per row
            const int colb = (ne * NT_U + ntl) * BN + wn * 64 + (l & 3) * 2;
#pragma unroll
            for (int mi = 0; mi < 2; mi++)
#pragma unroll
                for (int r2 = 0; r2 < 2; r2++) {
                    const int ri = mi * 2 + r2;
#pragma unroll
                    for (int nf = 0; nf < 8; nf++)
#pragma unroll
                        for (int d = 0; d < 2; d++) {
                            const int col = colb + nf * 8 + d;
                            float dist = __ldg(&g_enorm[col]) - 2.f * acc[mi][nf][r2 * 2 + d];
                            if (dist < td[ri][0]) {
                                td[ri][1] = td[ri][0]; ti[ri][1] = ti[ri][0];
                                td[ri][0] = dist;      ti[ri][0] = col;
                            } else if (dist < td[ri][1]) {
                                td[ri][1] = dist; ti[ri][1] = col;
                            }
                        }
                }
        }

        // intra-warp merge: 4-lane groups (same rows, different cols) -> top-2
#pragma unroll
        for (int ri = 0; ri < 4; ++ri) {
            float d0 = td[ri][0], d1 = td[ri][1];
            int   i0 = ti[ri][0], i1 = ti[ri][1];
#pragma unroll
            for (int off = 1; off <= 2; off <<= 1) {
                float od0 = __shfl_xor_sync(0xffffffffu, d0, off);
                float od1 = __shfl_xor_sync(0xffffffffu, d1, off);
                int   oi0 = __shfl_xor_sync(0xffffffffu, i0, off);
                int   oi1 = __shfl_xor_sync(0xffffffffu, i1, off);
                if (od0 < d0 || (od0 == d0 && oi0 < i0)) {
                    float nd1; int ni1;
                    if (d0 < od1 || (d0 == od1 && i0 < oi1)) { nd1 = d0; ni1 = i0; }
                    else                                      { nd1 = od1; ni1 = oi1; }
                    d0 = od0; i0 = oi0; d1 = nd1; i1 = ni1;
                } else if (od0 < d1 || (od0 == d1 && oi0 < i1)) {
                    d1 = od0; i1 = oi0;
                }
            }
            if ((l & 3) == 0) {
                const int row = wm * 32 + (ri >> 1) * 16 + (ri & 1) * 8 + (l >> 2);
                sMD[row * 4 + wn * 2]     = d0; sMI[row * 4 + wn * 2]     = i0;
                sMD[row * 4 + wn * 2 + 1] = d1; sMI[row * 4 + wn * 2 + 1] = i1;
            }
        }
        __syncthreads();
        if (tid < BM) {
            float dv[4]; int iv[4];
#pragma unroll
            for (int t = 0; t < 4; t++) { dv[t] = sMD[tid * 4 + t]; iv[t] = sMI[tid * 4 + t]; }
            const size_t rg = (size_t)(m * BM + tid) * 16 + ne * 2;
#pragma unroll
            for (int q = 0; q < 2; q++) {
                float bd = dv[0]; int bi = iv[0], bt = 0;
#pragma unroll
                for (int t = 1; t < 4; t++)
                    if (dv[t] < bd || (dv[t] == bd && iv[t] < bi)) { bd = dv[t]; bi = iv[t]; bt = t; }
                g_pd[rg + q] = bd; g_pi[rg + q] = bi;
                dv[bt] = 3.4e38f;
            }
        }
        __syncthreads();   // protect sMD/sMI reuse by next unit
    }
}

// ---------------------------------------------------------------------------
// Merge 16 per-unit candidates -> approx top-4 per row.
// ---------------------------------------------------------------------------
__global__ void mergecand_kernel() {
    const int row = blockIdx.x * 256 + threadIdx.x;
    if (row >= N_ROWS) return;
    float dv[16]; int iv[16];
#pragma unroll
    for (int t = 0; t < 16; t++) { dv[t] = g_pd[(size_t)row * 16 + t]; iv[t] = g_pi[(size_t)row * 16 + t]; }
#pragma unroll
    for (int q = 0; q < 4; q++) {
        float bd = dv[0]; int bi = iv[0], bt = 0;
#pragma unroll
        for (int t = 1; t < 16; t++)
            if (dv[t] < bd || (dv[t] == bd && iv[t] < bi)) { bd = dv[t]; bi = iv[t]; bt = t; }
        g_cand[row * 4 + q] = bi;
        dv[bt] = 3.4e38f;
    }
}

// ---------------------------------------------------------------------------
// Exact fp32 rescore of the 4 candidates per row.
// ---------------------------------------------------------------------------
__global__ void rescore_kernel(const float* __restrict__ x, const float* __restrict__ e) {
    const int row = blockIdx.x * 8 + (threadIdx.x >> 5);
    const int lane = threadIdx.x & 31;
    int c[4];
#pragma unroll
    for (int j = 0; j < 4; j++) c[j] = g_cand[row * 4 + j];
    const float* xr = x + (size_t)row * D_DIM;
    float s[4] = {0.f, 0.f, 0.f, 0.f};
    for (int d = lane; d < D_DIM; d += 32) {
        float xv = xr[d];
#pragma unroll
        for (int j = 0; j < 4; j++) s[j] += xv * e[(size_t)c[j] * D_DIM + d];
    }
#pragma unroll
    for (int o = 16; o; o >>= 1)
#pragma unroll
        for (int j = 0; j < 4; j++) s[j] += __shfl_down_sync(0xffffffffu, s[j], o);
    if (lane == 0) {
        float bd = 3.4e38f; int bi = 0x7fffffff;
#pragma unroll
        for (int j = 0; j < 4; j++) {
            float dj = g_enorm[c[j]] - 2.f * s[j];
            if (dj < bd || (dj == bd && c[j] < bi)) { bd = dj; bi = c[j]; }
        }
        g_bestIdx[row] = bi;
    }
}

// ---------------------------------------------------------------------------
// Writeout: out = [x_q, z_e, z_q]
// ---------------------------------------------------------------------------
__global__ void writeout_kernel(const float* __restrict__ x,
                                const float* __restrict__ e,
                                float* __restrict__ out) {
    const int ND4 = N_ROWS * (D_DIM / 4);
    int i = blockIdx.x * blockDim.x + threadIdx.x;
    if (i >= ND4) return;
    const int n = i >> 7, d4 = i & 127;
    const int idx = g_bestIdx[n];
    float4 xv = ((const float4*)x)[i];
    float4 ev = ((const float4*)e)[(size_t)idx * 128 + d4];
    float4 xq;
    xq.x = xv.x + (ev.x - xv.x);
    xq.y = xv.y + (ev.y - xv.y);
    xq.z = xv.z + (ev.z - xv.z);
    xq.w = xv.w + (ev.w - xv.w);
    float4* o = (float4*)out;
    o[i] = xq;               // x_q
    o[ND4 + i] = xv;         // z_e
    o[2 * ND4 + i] = ev;     // z_q
}

extern "C" void kernel_launch(void* const* d_in, const int* in_sizes, int n_in,
                              void* d_out, int out_size) {
    const float* x = (const float*)d_in[0];
    const float* e = (const float*)d_in[1];
    float* out = (float*)d_out;

    cudaFuncSetAttribute(gemm_argmin_kernel,
                         cudaFuncAttributeMaxDynamicSharedMemorySize, SMEM_TOTAL);

    split_x_kernel<<<N_ROWS * 64 / 256, 256>>>(x);
    split_e_kernel<<<K_EMB * 64 / 256, 256>>>(e);
    enorm_kernel<<<K_EMB, 128>>>(e);
    gemm_argmin_kernel<<<GRID_P, 256, SMEM_TOTAL>>>();
    mergecand_kernel<<<N_ROWS / 256, 256>>>();
    rescore_kernel<<<N_ROWS / 8, 256>>>(x, e);
    const int ND4 = N_ROWS * (D_DIM / 4);
    writeout_kernel<<<(ND4 + 255) / 256, 256>>>(x, e, out);
}